// round 5
// baseline (speedup 1.0000x reference)
#include <cuda_runtime.h>
#include <cstdint>

#define BZ     64
#define NC     2048
#define H      14
#define HW     196
#define NCLS   1000
#define SPLITS 4
#define CPB    512
#define TILE_C 8
#define NSTAGE 64            // CPB / TILE_C
#define NBUF   8
#define DIST   6
#define TPB    256
#define SW     198           // smem words per channel (conflict-free LDS.64)
#define NPAIR  105
#define NACC   27
#define MARGINV 70.0f
#define THRV    125.0f
#define PD_EPS  1e-6f

typedef unsigned long long ull;

// scratch (device globals; no allocations allowed)
__device__ float g_G[BZ * SPLITS * NPAIR];
__device__ float g_cam[BZ * SPLITS * 3 * HW];
__device__ float g_rs[BZ * SPLITS * H];
__device__ float g_cem[BZ * SPLITS];
__device__ float g_ces[BZ * SPLITS];
__device__ float g_r[BZ];
__device__ int   g_cnt_b[BZ];
__device__ int   g_cnt_all;

// ---------------- f32x2 helpers ----------------
__device__ __forceinline__ ull pk2(float lo, float hi) {
    ull r; asm("mov.b64 %0,{%1,%2};" : "=l"(r) : "f"(lo), "f"(hi)); return r;
}
__device__ __forceinline__ void upk2(float& lo, float& hi, ull v) {
    asm("mov.b64 {%0,%1},%2;" : "=f"(lo), "=f"(hi) : "l"(v));
}
__device__ __forceinline__ ull fma2(ull a, ull b, ull c) {
    ull d; asm("fma.rn.f32x2 %0,%1,%2,%3;" : "=l"(d) : "l"(a), "l"(b), "l"(c)); return d;
}
__device__ __forceinline__ ull add2(ull a, ull b) {
    ull d; asm("add.rn.f32x2 %0,%1,%2;" : "=l"(d) : "l"(a), "l"(b)); return d;
}

// ---------------------------------------------------------------------------
// cp.async 8B prefetch of one 8-channel tile into stride-SW smem
// ---------------------------------------------------------------------------
__device__ __forceinline__ void prefetch_tile(const float* __restrict__ src,
                                              float* dst, int t) {
#pragma unroll
    for (int it = 0; it < 4; it++) {
        int u = t + it * TPB;            // 784 ull transfers (8 ch x 98)
        if (u < TILE_C * 98) {
            int cc = u / 98;
            int o  = u - cc * 98;
            const float* s = src + cc * HW + 2 * o;
            unsigned d = (unsigned)__cvta_generic_to_shared(dst + cc * SW + 2 * o);
            asm volatile("cp.async.ca.shared.global [%0], [%1], 8;\n"
                         :: "r"(d), "l"(s));
        }
    }
}

// Gram quarter: pairs p in [LO,HI). c2[k] = {F[k,j], F[k,j+1]}; acc packed over j-parity.
template<int LO, int HI>
__device__ __forceinline__ void gram_q(const float* __restrict__ base,
                                       ull* __restrict__ acc) {
    ull c2[H];
#pragma unroll
    for (int k = 0; k < H; k++)
        c2[k] = *(const ull*)(base + k * H);
#pragma unroll
    for (int k = 0; k < H; k++) {
#pragma unroll
        for (int l = k; l < H; l++) {
            int p = k * H - (k * (k - 1)) / 2 + (l - k);
            if (p >= LO && p < HI)
                acc[p - LO] = fma2(c2[k], c2[l], acc[p - LO]);
        }
    }
}

// ---------------------------------------------------------------------------
// Fused kernel: streaming pass + per-batch finalize (ticketed) + global mean
// smem (floats): tiles[0,12672) wpk/wqk[12672,14720) ce[14720,14976)
// reuse after main loop: slab (4*56*27 ull = 48384B), then finalize arrays
// ---------------------------------------------------------------------------
__global__ void __launch_bounds__(TPB, 2)
k1_fused(const float* __restrict__ feat,
         const float* __restrict__ W,
         const int*   __restrict__ idx,
         const float* __restrict__ pred,
         const int*   __restrict__ cla,
         const float* __restrict__ seg,
         float*       __restrict__ out) {
    extern __shared__ float sh[];
    float* tiles = sh;
    ull*   wpk   = (ull*)(sh + NBUF * TILE_C * SW);     // {w0,w1} per channel
    ull*   wqk   = wpk + CPB;                           // {w2,1}
    float* cesh  = sh + NBUF * TILE_C * SW + 4 * CPB;   // 256 floats

    const int t   = threadIdx.x;
    const int blk = blockIdx.x;
    const int b   = blk >> 2;
    const int s   = blk & 3;
    const int c0  = s * CPB;

    const int q  = t >> 6;        // pair quarter (2 warps each -> uniform)
    const int r  = t & 63;
    const int jp = r >> 3;        // column pair (0..6 valid, 7 idle)
    const int cl = r & 7;         // channel in tile

    // weight gather (packed)
    {
        const int i0 = idx[b * 3 + 0];
        const int i1 = idx[b * 3 + 1];
        const int i2 = idx[b * 3 + 2];
        const float* w0 = W + (size_t)i0 * NC;
        const float* w1 = W + (size_t)i1 * NC;
        const float* w2 = W + (size_t)i2 * NC;
        for (int cc = t; cc < CPB; cc += TPB) {
            int c = c0 + cc;
            wpk[cc] = pk2(w0[c], w1[c]);
            wqk[cc] = pk2(w2[c], 1.0f);
        }
    }

    const float* fbase = feat + ((size_t)b * NC + c0) * HW;

    // prime pipeline: DIST tiles
#pragma unroll
    for (int pf = 0; pf < DIST; pf++) {
        prefetch_tile(fbase + (size_t)pf * TILE_C * HW, tiles + pf * TILE_C * SW, t);
        asm volatile("cp.async.commit_group;\n");
    }

    // CE partial over classes [s*250, s*250+250) — overlaps prefetch
    {
        const float* prow = pred + (size_t)b * NCLS + s * 250;
        float x = (t < 250) ? prow[t] : -1e30f;
        float m = x;
#pragma unroll
        for (int off = 16; off >= 1; off >>= 1)
            m = fmaxf(m, __shfl_xor_sync(0xffffffffu, m, off));
        if ((t & 31) == 0) cesh[t >> 5] = m;
        __syncthreads();
        float mx = cesh[0];
#pragma unroll
        for (int w = 1; w < 8; w++) mx = fmaxf(mx, cesh[w]);
        float e = (t < 250) ? expf(x - mx) : 0.0f;
#pragma unroll
        for (int off = 16; off >= 1; off >>= 1)
            e += __shfl_xor_sync(0xffffffffu, e, off);
        __syncthreads();
        if ((t & 31) == 0) cesh[8 + (t >> 5)] = e;
        __syncthreads();
        if (t == 0) {
            float sum = 0.f;
#pragma unroll
            for (int w = 0; w < 8; w++) sum += cesh[8 + w];
            g_cem[blk] = mx;
            g_ces[blk] = sum;
        }
    }

    ull acc[NACC];
#pragma unroll
    for (int i = 0; i < NACC; i++) acc[i] = 0ull;
    ull cam01 = 0ull, cam2r = 0ull;

#pragma unroll 1
    for (int st = 0; st < NSTAGE; st++) {
        if (st + DIST < NSTAGE) {
            int wb = st + DIST;
            prefetch_tile(fbase + (size_t)wb * TILE_C * HW,
                          tiles + (wb & (NBUF - 1)) * TILE_C * SW, t);
            asm volatile("cp.async.commit_group;\n");
            asm volatile("cp.async.wait_group %0;\n" :: "n"(DIST));
        } else if (st + 5 < NSTAGE) { asm volatile("cp.async.wait_group 5;\n");
        } else if (st + 4 < NSTAGE) { asm volatile("cp.async.wait_group 4;\n");
        } else if (st + 3 < NSTAGE) { asm volatile("cp.async.wait_group 3;\n");
        } else if (st + 2 < NSTAGE) { asm volatile("cp.async.wait_group 2;\n");
        } else if (st + 1 < NSTAGE) { asm volatile("cp.async.wait_group 1;\n");
        } else                      { asm volatile("cp.async.wait_group 0;\n"); }
        __syncthreads();

        const float* buf = tiles + (st & (NBUF - 1)) * TILE_C * SW;

        // ---- Gram: conflict-free LDS.64 column-pairs, packed partials ----
        if (jp < 7) {
            const float* base = buf + cl * SW + 2 * jp;
            if      (q == 0) gram_q<0,  27 >(base, acc);
            else if (q == 1) gram_q<27, 53 >(base, acc);
            else if (q == 2) gram_q<53, 79 >(base, acc);
            else             gram_q<79, 105>(base, acc);
        }

        // ---- CAM + rowsum: pixel-parallel ----
        if (t < HW) {
            const ull* wp = wpk + st * TILE_C;
            const ull* wq = wqk + st * TILE_C;
#pragma unroll
            for (int cc = 0; cc < TILE_C; cc++) {
                float f = buf[cc * SW + t];
                ull fs = pk2(f, f);
                cam01 = fma2(fs, wp[cc], cam01);
                cam2r = fma2(fs, wq[cc], cam2r);
            }
        }
    }
    __syncthreads();

    // ---- cam + rowsum outputs ----
    if (t < HW) {
        float a, bb, c, rs;
        upk2(a, bb, cam01);
        upk2(c, rs, cam2r);
        float* co = g_cam + (size_t)blk * 3 * HW;
        co[t]          = a;
        co[HW + t]     = bb;
        co[2 * HW + t] = c;
        sh[t] = rs;
    }
    __syncthreads();
    if (t < H) {
        float v = 0.f;
#pragma unroll
        for (int j = 0; j < H; j++) v += sh[t * H + j];
        g_rs[blk * H + t] = v;
    }
    __syncthreads();

    // ---- Gram reduce: dump 56 contributors/quarter, 105 threads fold ----
    ull* slab = (ull*)sh;                         // [4][56][27] ull = 48384B
    if (jp < 7) {
        ull* d = slab + ((size_t)q * 56 + jp * 8 + cl) * NACC;
#pragma unroll
        for (int i = 0; i < NACC; i++) d[i] = acc[i];
    }
    __syncthreads();
    if (t < NPAIR) {
        int qq, off;
        if      (t < 27) { qq = 0; off = t;      }
        else if (t < 53) { qq = 1; off = t - 27; }
        else if (t < 79) { qq = 2; off = t - 53; }
        else             { qq = 3; off = t - 79; }
        const ull* sp = slab + (size_t)qq * 56 * NACC + off;
        ull v = 0ull;
#pragma unroll 8
        for (int i = 0; i < 56; i++) v = add2(v, sp[(size_t)i * NACC]);
        float a, bb; upk2(a, bb, v);
        g_G[(size_t)blk * NPAIR + t] = a + bb;
    }
    __syncthreads();

    // ---- ticket: last block of this batch runs finalize ----
    __shared__ int sflag;
    if (t == 0) {
        __threadfence();
        int old = atomicAdd(&g_cnt_b[b], 1);
        sflag = (old == 3);
        if (old == 3) atomicExch(&g_cnt_b[b], 0);   // reset for graph replay
    }
    __syncthreads();
    if (!sflag) return;

    // =================== finalize (old K2 body) ===================
    float* camr = sh;               // 3*196
    float* D01s = sh + 588;         // 196
    float* D02s = sh + 784;         // 196
    float* dstb = sh + 980;         // 196
    float* Gs   = sh + 1176;        // 105
    float* rss  = sh + 1281;        // 14
    float* red  = sh + 1295;        // 256
    float* red2 = sh + 1551;        // 256
    float* bc   = sh + 1807;        // 8

    if (t < HW) {
#pragma unroll
        for (int j = 0; j < 3; j++) {
            float v = 0.f;
#pragma unroll
            for (int ss = 0; ss < SPLITS; ss++)
                v += g_cam[((size_t)(b * SPLITS + ss) * 3 + j) * HW + t];
            camr[j * HW + t] = v;
        }
    }
    if (t < NPAIR) {
        float v = 0.f;
#pragma unroll
        for (int ss = 0; ss < SPLITS; ss++) v += g_G[(size_t)(b * SPLITS + ss) * NPAIR + t];
        Gs[t] = v;
    }
    if (t < H) {
        float v = 0.f;
#pragma unroll
        for (int ss = 0; ss < SPLITS; ss++) v += g_rs[(b * SPLITS + ss) * H + t];
        rss[t] = v;
    }
    __syncthreads();

    if (t < 32) {
        float mn0 = 1e30f, mn1 = 1e30f, mn2 = 1e30f;
        float mx0 = -1e30f, mx1 = -1e30f, mx2 = -1e30f;
        for (int p = t; p < HW; p += 32) {
            float v0 = camr[p], v1 = camr[HW + p], v2 = camr[2 * HW + p];
            mn0 = fminf(mn0, v0); mx0 = fmaxf(mx0, v0);
            mn1 = fminf(mn1, v1); mx1 = fmaxf(mx1, v1);
            mn2 = fminf(mn2, v2); mx2 = fmaxf(mx2, v2);
        }
#pragma unroll
        for (int off = 16; off >= 1; off >>= 1) {
            mn0 = fminf(mn0, __shfl_xor_sync(0xffffffffu, mn0, off));
            mx0 = fmaxf(mx0, __shfl_xor_sync(0xffffffffu, mx0, off));
            mn1 = fminf(mn1, __shfl_xor_sync(0xffffffffu, mn1, off));
            mx1 = fmaxf(mx1, __shfl_xor_sync(0xffffffffu, mx1, off));
            mn2 = fminf(mn2, __shfl_xor_sync(0xffffffffu, mn2, off));
            mx2 = fmaxf(mx2, __shfl_xor_sync(0xffffffffu, mx2, off));
        }
        if (t == 0) {
            bc[0] = mn0; bc[1] = mn1; bc[2] = mn2;
            bc[3] = 255.f / (mx0 - mn0);
            bc[4] = 255.f / (mx1 - mn1);
            bc[5] = 255.f / (mx2 - mn2);
        }
    }
    __syncthreads();

    if (t < HW) {
        float v0 = (camr[t] - bc[0]) * bc[3];
        float v1 = (camr[HW + t] - bc[1]) * bc[4];
        float v2 = (camr[2 * HW + t] - bc[2]) * bc[5];
        D01s[t] = v0 - v1;
        D02s[t] = v0 - v2;
        dstb[t] = (v0 > THRV) ? 1.f : 0.f;
    }
    __syncthreads();

    float c01 = 0.f, c02 = 0.f;
    if (t < NPAIR) {
        int k = 0, rem = t;
        while (rem >= H - k) { rem -= H - k; k++; }
        int l = k + rem;
        float m01 = 0.f, m02 = 0.f;
#pragma unroll
        for (int i = 0; i < H; i++) {
            m01 = fmaf(D01s[i * H + k], D01s[i * H + l], m01);
            m02 = fmaf(D02s[i * H + k], D02s[i * H + l], m02);
        }
        float wgt = (k == l) ? 1.f : 2.f;
        c01 = wgt * m01 * Gs[t];
        c02 = wgt * m02 * Gs[t];
    }
    red[t]  = c01;
    red2[t] = c02;
    __syncthreads();
    if (t < 32) {
        float s1 = 0.f, s2 = 0.f;
        for (int p = t; p < NPAIR; p += 32) { s1 += red[p]; s2 += red2[p]; }
#pragma unroll
        for (int off = 16; off >= 1; off >>= 1) {
            s1 += __shfl_xor_sync(0xffffffffu, s1, off);
            s2 += __shfl_xor_sync(0xffffffffu, s2, off);
        }
        if (t == 0) { bc[6] = s1; bc[7] = s2; }
    }
    __syncthreads();

    if (t < H) {
        const float* srow = seg + (size_t)b * HW + t * H;
        float a = 0.f;
#pragma unroll
        for (int w = 0; w < H; w++) {
            float d = dstb[t * H + w] - srow[w] + PD_EPS;
            a = fmaf(d, d, a);
        }
        red[t] = sqrtf(a);
    }
    __syncthreads();

    __shared__ int sflag2;
    if (t == 0) {
        float m0 = g_cem[b * 4 + 0], m1 = g_cem[b * 4 + 1];
        float m2 = g_cem[b * 4 + 2], m3 = g_cem[b * 4 + 3];
        float M = fmaxf(fmaxf(m0, m1), fmaxf(m2, m3));
        float S = g_ces[b * 4 + 0] * expf(m0 - M) + g_ces[b * 4 + 1] * expf(m1 - M)
                + g_ces[b * 4 + 2] * expf(m2 - M) + g_ces[b * 4 + 3] * expf(m3 - M);
        float ce = M + logf(S) - pred[(size_t)b * NCLS + cla[b]];

        float ed1 = 0.f;
#pragma unroll
        for (int hh = 0; hh < H; hh++) ed1 += red[hh];
        ed1 *= (1.f / H);

        float e01 = 0.f, e02 = 0.f;
#pragma unroll
        for (int k = 0; k < H; k++) {
            float s01 = 0.f, s02 = 0.f;
#pragma unroll
            for (int i = 0; i < H; i++) {
                s01 += D01s[i * H + k];
                s02 += D02s[i * H + k];
            }
            e01 = fmaf(s01, rss[k], e01);
            e02 = fmaf(s02, rss[k], e02);
        }
        const float epsq = PD_EPS * PD_EPS * (float)(HW * NC);
        float d01 = sqrtf(bc[6] + 2.f * PD_EPS * e01 + epsq) * (1.f / NC);
        float d02 = sqrtf(bc[7] + 2.f * PD_EPS * e02 + epsq) * (1.f / NC);
        g_r[b] = ed1 + fmaxf(MARGINV - d01 - d02, 0.f) + ce;

        __threadfence();
        int o2 = atomicAdd(&g_cnt_all, 1);
        sflag2 = (o2 == BZ - 1);
        if (o2 == BZ - 1) atomicExch(&g_cnt_all, 0);
    }
    __syncthreads();

    if (sflag2 && t == 0) {
        float v = 0.f;
#pragma unroll
        for (int i = 0; i < BZ; i++) v += g_r[i];
        out[0] = v * (1.f / BZ);
    }
}

// ---------------------------------------------------------------------------
extern "C" void kernel_launch(void* const* d_in, const int* in_sizes, int n_in,
                              void* d_out, int out_size) {
    const float* pred = (const float*)d_in[0];
    const int*   cla  = (const int*)  d_in[1];
    const float* seg  = (const float*)d_in[2];
    const float* feat = (const float*)d_in[3];
    const float* W    = (const float*)d_in[4];
    const int*   idx  = (const int*)  d_in[5];
    float* out = (float*)d_out;

    // tiles 8*8*198 + w 2048 + ce 256 = 14976 floats = 59904 B
    const int smem = (NBUF * TILE_C * SW + 4 * CPB + 256) * (int)sizeof(float);
    cudaFuncSetAttribute(k1_fused, cudaFuncAttributeMaxDynamicSharedMemorySize, smem);

    k1_fused<<<BZ * SPLITS, TPB, smem>>>(feat, W, idx, pred, cla, seg, out);
}

// round 6
// speedup vs baseline: 1.3216x; 1.3216x over previous
#include <cuda_runtime.h>
#include <cstdint>

#define BZ     64
#define NC     2048
#define H      14
#define HW     196
#define NCLS   1000
#define SPLITS 4
#define CPB    512
#define TILE_C 16
#define NSTAGE 32            // CPB / TILE_C
#define NBUF   5
#define TPB    256
#define PADW   200
#define NPAIR  105
#define MARGINV 70.0f
#define THRV    125.0f
#define PD_EPS  1e-6f

typedef unsigned long long ull;

// scratch (device globals; no allocations allowed)
__device__ float g_G[BZ * SPLITS * NPAIR];
__device__ float g_cam[BZ * SPLITS * 3 * HW];
__device__ float g_rs[BZ * SPLITS * H];
__device__ float g_cem[BZ * SPLITS];
__device__ float g_ces[BZ * SPLITS];
__device__ float g_r[BZ];
__device__ int   g_cnt_b[BZ];
__device__ int   g_cnt_all;

// ---------------- f32x2 helpers ----------------
__device__ __forceinline__ ull pk2(float lo, float hi) {
    ull r; asm("mov.b64 %0,{%1,%2};" : "=l"(r) : "f"(lo), "f"(hi)); return r;
}
__device__ __forceinline__ void upk2(float& lo, float& hi, ull v) {
    asm("mov.b64 {%0,%1},%2;" : "=f"(lo), "=f"(hi) : "l"(v));
}
__device__ __forceinline__ ull fma2(ull a, ull b, ull c) {
    ull d; asm("fma.rn.f32x2 %0,%1,%2,%3;" : "=l"(d) : "l"(a), "l"(b), "l"(c)); return d;
}
__device__ __forceinline__ ull add2(ull a, ull b) {
    ull d; asm("add.rn.f32x2 %0,%1,%2;" : "=l"(d) : "l"(a), "l"(b)); return d;
}

// packed-acc offsets: half0 (k even): O0(kk)=7kk-kk(kk-1)/2 ; half1: O1(kk)=6kk-kk(kk-1)/2
__device__ __forceinline__ int O0f(int kk) { return 7 * kk - (kk * (kk - 1)) / 2; }
__device__ __forceinline__ int O1f(int kk) { return 6 * kk - (kk * (kk - 1)) / 2; }

// ---------------------------------------------------------------------------
// cp.async prefetch of one 16-channel tile (16 x 196 floats) into padded smem
// ---------------------------------------------------------------------------
__device__ __forceinline__ void prefetch_tile(const float* __restrict__ src_base,
                                              float* dst, int t) {
#pragma unroll
    for (int it = 0; it < 4; it++) {
        int q = t + it * TPB;            // 784 float4 transfers (16*49)
        if (q < TILE_C * 49) {
            int cc = q / 49;
            int p4 = q - cc * 49;
            const float* src = src_base + cc * HW + p4 * 4;
            unsigned dsts = (unsigned)__cvta_generic_to_shared(dst + cc * PADW + p4 * 4);
            asm volatile("cp.async.cg.shared.global [%0], [%1], 16;\n"
                         :: "r"(dsts), "l"(src));
        }
    }
}

// one column jj of one channel: load 14 strided floats packed, accumulate pairs
template<int HALF>
__device__ __forceinline__ void gram_col(const float* __restrict__ base, int jj,
                                         ull* __restrict__ ap, float* __restrict__ ad) {
    ull c2[7];
#pragma unroll
    for (int m = 0; m < 7; m++) {
        float a = base[(2 * m) * H + jj];
        float b = base[(2 * m + 1) * H + jj];
        c2[m] = pk2(a, b);
    }
    if (HALF == 0) {
#pragma unroll
        for (int kk = 0; kk < 7; kk++) {     // k = 2kk
            float lo, hi; upk2(lo, hi, c2[kk]);
            ull sp = pk2(lo, lo);
#pragma unroll
            for (int m = kk; m < 7; m++)
                ap[O0f(kk) + m - kk] = fma2(sp, c2[m], ap[O0f(kk) + m - kk]);
        }
    } else {
#pragma unroll
        for (int kk = 0; kk < 7; kk++) {     // k = 2kk+1
            float lo, hi; upk2(lo, hi, c2[kk]);
            ad[kk] = fmaf(hi, hi, ad[kk]);   // diagonal (k,k)
            ull sp = pk2(hi, hi);
#pragma unroll
            for (int m = kk + 1; m < 7; m++)
                ap[O1f(kk) + m - kk - 1] = fma2(sp, c2[m], ap[O1f(kk) + m - kk - 1]);
        }
    }
}

// ---------------------------------------------------------------------------
// Fused kernel: streaming pass (R4 structure) + ticketed per-batch finalize
// ---------------------------------------------------------------------------
__global__ void __launch_bounds__(TPB, 2)
k1_fused(const float* __restrict__ feat,
         const float* __restrict__ W,
         const int*   __restrict__ idx,
         const float* __restrict__ pred,
         const int*   __restrict__ cla,
         const float* __restrict__ seg,
         float*       __restrict__ out) {
    extern __shared__ float sh[];
    float* tiles = sh;
    ull*   wpk   = (ull*)(sh + NBUF * TILE_C * PADW);          // {w0,w1}
    ull*   wqk   = wpk + CPB;                                  // {w2,1}
    float* cesh  = sh + NBUF * TILE_C * PADW + 4 * CPB;        // 256 floats

    const int t   = threadIdx.x;
    const int blk = blockIdx.x;
    const int b   = blk >> 2;
    const int s   = blk & 3;
    const int c0  = s * CPB;

    const int half = t >> 7;
    const int r    = t & 127;
    const int cl   = r >> 3;       // channel in tile (0..15)
    const int jg   = r & 7;        // column group

    // weight gather (packed)
    {
        const int i0 = idx[b * 3 + 0];
        const int i1 = idx[b * 3 + 1];
        const int i2 = idx[b * 3 + 2];
        const float* w0 = W + (size_t)i0 * NC;
        const float* w1 = W + (size_t)i1 * NC;
        const float* w2 = W + (size_t)i2 * NC;
        for (int cc = t; cc < CPB; cc += TPB) {
            int c = c0 + cc;
            wpk[cc] = pk2(w0[c], w1[c]);
            wqk[cc] = pk2(w2[c], 1.0f);
        }
    }

    const float* fbase = feat + ((size_t)b * NC + c0) * HW;

    // prime pipeline (prefetch distance 3, 5 buffers)
    prefetch_tile(fbase,                   tiles,                     t);
    asm volatile("cp.async.commit_group;\n");
    prefetch_tile(fbase +     TILE_C * HW, tiles +     TILE_C * PADW, t);
    asm volatile("cp.async.commit_group;\n");
    prefetch_tile(fbase + 2 * TILE_C * HW, tiles + 2 * TILE_C * PADW, t);
    asm volatile("cp.async.commit_group;\n");

    // ---- CE partial over classes [s*250, s*250+250) (overlaps prefetch) ----
    {
        const float* prow = pred + (size_t)b * NCLS + s * 250;
        float x = (t < 250) ? prow[t] : -1e30f;
        float m = x;
#pragma unroll
        for (int off = 16; off >= 1; off >>= 1)
            m = fmaxf(m, __shfl_xor_sync(0xffffffffu, m, off));
        if ((t & 31) == 0) cesh[t >> 5] = m;
        __syncthreads();
        float mx = cesh[0];
#pragma unroll
        for (int w = 1; w < 8; w++) mx = fmaxf(mx, cesh[w]);
        float e = (t < 250) ? expf(x - mx) : 0.0f;
#pragma unroll
        for (int off = 16; off >= 1; off >>= 1)
            e += __shfl_xor_sync(0xffffffffu, e, off);
        __syncthreads();
        if ((t & 31) == 0) cesh[8 + (t >> 5)] = e;
        __syncthreads();
        if (t == 0) {
            float sum = 0.f;
#pragma unroll
            for (int w = 0; w < 8; w++) sum += cesh[8 + w];
            g_cem[blk] = mx;
            g_ces[blk] = sum;
        }
    }

    ull  ap[28];
    float ad[7];
#pragma unroll
    for (int i = 0; i < 28; i++) ap[i] = 0ull;
#pragma unroll
    for (int i = 0; i < 7; i++) ad[i] = 0.f;
    ull cam01 = 0ull, cam2r = 0ull;

    int rdbuf = 0;
#pragma unroll 1
    for (int st = 0; st < NSTAGE; st++) {
        if (st + 3 < NSTAGE) {
            int wb = st + 3;
            int wbuf = wb - (wb / NBUF) * NBUF;
            prefetch_tile(fbase + (size_t)wb * TILE_C * HW,
                          tiles + wbuf * TILE_C * PADW, t);
            asm volatile("cp.async.commit_group;\n");
            asm volatile("cp.async.wait_group 3;\n");
        } else if (st + 2 < NSTAGE) {
            asm volatile("cp.async.wait_group 2;\n");
        } else if (st + 1 < NSTAGE) {
            asm volatile("cp.async.wait_group 1;\n");
        } else {
            asm volatile("cp.async.wait_group 0;\n");
        }
        __syncthreads();

        const float* buf = tiles + rdbuf * TILE_C * PADW;
        rdbuf = (rdbuf + 1 == NBUF) ? 0 : rdbuf + 1;

        // ---- Gram (packed f32x2, half-split over k-parity) ----
        {
            const float* base = buf + cl * PADW;
            if (half == 0) {
                gram_col<0>(base, jg, ap, ad);
                if (jg < 6) gram_col<0>(base, jg + 8, ap, ad);
            } else {
                gram_col<1>(base, jg, ap, ad);
                if (jg < 6) gram_col<1>(base, jg + 8, ap, ad);
            }
        }

        // ---- CAM + rowsum (packed) ----
        if (t < HW) {
            const ull* wp = wpk + st * TILE_C;
            const ull* wq = wqk + st * TILE_C;
#pragma unroll
            for (int cc = 0; cc < TILE_C; cc++) {
                float f = buf[cc * PADW + t];
                ull fs = pk2(f, f);
                cam01 = fma2(fs, wp[cc], cam01);
                cam2r = fma2(fs, wq[cc], cam2r);
            }
        }
    }
    __syncthreads();   // all reads of last tile done before smem repurpose

    // ---- cam + rowsum outputs ----
    if (t < HW) {
        float a, bb, c, rs;
        upk2(a, bb, cam01);
        upk2(c, rs, cam2r);
        float* co = g_cam + (size_t)blk * 3 * HW;
        co[t]          = a;
        co[HW + t]     = bb;
        co[2 * HW + t] = c;
        sh[t] = rs;
    }
    __syncthreads();
    if (t < H) {
        float v = 0.f;
#pragma unroll
        for (int j = 0; j < H; j++) v += sh[t * H + j];
        g_rs[blk * H + t] = v;
    }
    __syncthreads();

    // ---- Gram dump (packed) ----
    ull*   slab0 = (ull*)sh;                   // 128 x 29
    ull*   slab1 = slab0 + 128 * 29;           // 128 x 22
    float* slabd = (float*)(slab1 + 128 * 22); // 128 x 8
    if (half == 0) {
        ull* d = slab0 + (size_t)r * 29;
#pragma unroll
        for (int i = 0; i < 28; i++) d[i] = ap[i];
    } else {
        ull* d = slab1 + (size_t)r * 22;
#pragma unroll
        for (int i = 0; i < 21; i++) d[i] = ap[i];
        float* dd = slabd + (size_t)r * 8;
#pragma unroll
        for (int i = 0; i < 7; i++) dd[i] = ad[i];
    }
    __syncthreads();

    float* gg = g_G + (size_t)blk * NPAIR;
    if (t < 28) {
        int tau = t;
        int kk = 0;
        while (kk < 6 && O0f(kk + 1) <= tau) kk++;
        int m = kk + (tau - O0f(kk));
        int k = 2 * kk, l0 = 2 * m;
        ull S = 0ull;
#pragma unroll 8
        for (int rr = 0; rr < 128; rr++) S = add2(S, slab0[(size_t)rr * 29 + tau]);
        float a, bb; upk2(a, bb, S);
        int qq = k * 14 - (k * (k - 1)) / 2 + (l0 - k);
        gg[qq] = a; gg[qq + 1] = bb;
    } else if (t >= 32 && t < 53) {
        int tau = t - 32;
        int kk = 0;
        while (kk < 6 && O1f(kk + 1) <= tau) kk++;
        int m = kk + 1 + (tau - O1f(kk));
        int k = 2 * kk + 1, l0 = 2 * m;
        ull S = 0ull;
#pragma unroll 8
        for (int rr = 0; rr < 128; rr++) S = add2(S, slab1[(size_t)rr * 22 + tau]);
        float a, bb; upk2(a, bb, S);
        int qq = k * 14 - (k * (k - 1)) / 2 + (l0 - k);
        gg[qq] = a; gg[qq + 1] = bb;
    } else if (t >= 64 && t < 71) {
        int kk = t - 64;
        int k = 2 * kk + 1;
        float v = 0.f;
#pragma unroll 8
        for (int rr = 0; rr < 128; rr++) v += slabd[(size_t)rr * 8 + kk];
        int qq = k * 14 - (k * (k - 1)) / 2;
        gg[qq] = v;
    }
    __syncthreads();

    // ---- ticket: last block of this batch runs finalize ----
    __shared__ int sflag;
    if (t == 0) {
        __threadfence();
        int old = atomicAdd(&g_cnt_b[b], 1);
        sflag = (old == 3);
        if (old == 3) atomicExch(&g_cnt_b[b], 0);   // reset for graph replay
    }
    __syncthreads();
    if (!sflag) return;
    __threadfence();   // acquire: other blocks' g_* writes

    // =================== finalize (per-batch) ===================
    float* camr = sh;               // 3*196
    float* D01s = sh + 588;
    float* D02s = sh + 784;
    float* dstb = sh + 980;
    float* Gs   = sh + 1176;
    float* rss  = sh + 1281;
    float* red  = sh + 1295;
    float* red2 = sh + 1551;
    float* bc   = sh + 1807;        // 8

    if (t < HW) {
#pragma unroll
        for (int j = 0; j < 3; j++) {
            float v = 0.f;
#pragma unroll
            for (int ss = 0; ss < SPLITS; ss++)
                v += g_cam[((size_t)(b * SPLITS + ss) * 3 + j) * HW + t];
            camr[j * HW + t] = v;
        }
    }
    if (t < NPAIR) {
        float v = 0.f;
#pragma unroll
        for (int ss = 0; ss < SPLITS; ss++) v += g_G[(size_t)(b * SPLITS + ss) * NPAIR + t];
        Gs[t] = v;
    }
    if (t < H) {
        float v = 0.f;
#pragma unroll
        for (int ss = 0; ss < SPLITS; ss++) v += g_rs[(b * SPLITS + ss) * H + t];
        rss[t] = v;
    }
    __syncthreads();

    if (t < 32) {
        float mn0 = 1e30f, mn1 = 1e30f, mn2 = 1e30f;
        float mx0 = -1e30f, mx1 = -1e30f, mx2 = -1e30f;
        for (int p = t; p < HW; p += 32) {
            float v0 = camr[p], v1 = camr[HW + p], v2 = camr[2 * HW + p];
            mn0 = fminf(mn0, v0); mx0 = fmaxf(mx0, v0);
            mn1 = fminf(mn1, v1); mx1 = fmaxf(mx1, v1);
            mn2 = fminf(mn2, v2); mx2 = fmaxf(mx2, v2);
        }
#pragma unroll
        for (int off = 16; off >= 1; off >>= 1) {
            mn0 = fminf(mn0, __shfl_xor_sync(0xffffffffu, mn0, off));
            mx0 = fmaxf(mx0, __shfl_xor_sync(0xffffffffu, mx0, off));
            mn1 = fminf(mn1, __shfl_xor_sync(0xffffffffu, mn1, off));
            mx1 = fmaxf(mx1, __shfl_xor_sync(0xffffffffu, mx1, off));
            mn2 = fminf(mn2, __shfl_xor_sync(0xffffffffu, mn2, off));
            mx2 = fmaxf(mx2, __shfl_xor_sync(0xffffffffu, mx2, off));
        }
        if (t == 0) {
            bc[0] = mn0; bc[1] = mn1; bc[2] = mn2;
            bc[3] = 255.f / (mx0 - mn0);
            bc[4] = 255.f / (mx1 - mn1);
            bc[5] = 255.f / (mx2 - mn2);
        }
    }
    __syncthreads();

    if (t < HW) {
        float v0 = (camr[t] - bc[0]) * bc[3];
        float v1 = (camr[HW + t] - bc[1]) * bc[4];
        float v2 = (camr[2 * HW + t] - bc[2]) * bc[5];
        D01s[t] = v0 - v1;
        D02s[t] = v0 - v2;
        dstb[t] = (v0 > THRV) ? 1.f : 0.f;
    }
    __syncthreads();

    float c01 = 0.f, c02 = 0.f;
    if (t < NPAIR) {
        int k = 0, rem = t;
        while (rem >= H - k) { rem -= H - k; k++; }
        int l = k + rem;
        float m01 = 0.f, m02 = 0.f;
#pragma unroll
        for (int i = 0; i < H; i++) {
            m01 = fmaf(D01s[i * H + k], D01s[i * H + l], m01);
            m02 = fmaf(D02s[i * H + k], D02s[i * H + l], m02);
        }
        float wgt = (k == l) ? 1.f : 2.f;
        c01 = wgt * m01 * Gs[t];
        c02 = wgt * m02 * Gs[t];
    }
    red[t]  = c01;
    red2[t] = c02;
    __syncthreads();
    if (t < 32) {
        float s1 = 0.f, s2 = 0.f;
        for (int p = t; p < NPAIR; p += 32) { s1 += red[p]; s2 += red2[p]; }
#pragma unroll
        for (int off = 16; off >= 1; off >>= 1) {
            s1 += __shfl_xor_sync(0xffffffffu, s1, off);
            s2 += __shfl_xor_sync(0xffffffffu, s2, off);
        }
        if (t == 0) { bc[6] = s1; bc[7] = s2; }
    }
    __syncthreads();

    if (t < H) {
        const float* srow = seg + (size_t)b * HW + t * H;
        float a = 0.f;
#pragma unroll
        for (int w = 0; w < H; w++) {
            float d = dstb[t * H + w] - srow[w] + PD_EPS;
            a = fmaf(d, d, a);
        }
        red[t] = sqrtf(a);
    }
    __syncthreads();

    __shared__ int sflag2;
    if (t == 0) {
        float m0 = g_cem[b * 4 + 0], m1 = g_cem[b * 4 + 1];
        float m2 = g_cem[b * 4 + 2], m3 = g_cem[b * 4 + 3];
        float M = fmaxf(fmaxf(m0, m1), fmaxf(m2, m3));
        float S = g_ces[b * 4 + 0] * expf(m0 - M) + g_ces[b * 4 + 1] * expf(m1 - M)
                + g_ces[b * 4 + 2] * expf(m2 - M) + g_ces[b * 4 + 3] * expf(m3 - M);
        float ce = M + logf(S) - pred[(size_t)b * NCLS + cla[b]];

        float ed1 = 0.f;
#pragma unroll
        for (int hh = 0; hh < H; hh++) ed1 += red[hh];
        ed1 *= (1.f / H);

        float e01 = 0.f, e02 = 0.f;
#pragma unroll
        for (int k = 0; k < H; k++) {
            float s01 = 0.f, s02 = 0.f;
#pragma unroll
            for (int i = 0; i < H; i++) {
                s01 += D01s[i * H + k];
                s02 += D02s[i * H + k];
            }
            e01 = fmaf(s01, rss[k], e01);
            e02 = fmaf(s02, rss[k], e02);
        }
        const float epsq = PD_EPS * PD_EPS * (float)(HW * NC);
        float d01 = sqrtf(bc[6] + 2.f * PD_EPS * e01 + epsq) * (1.f / NC);
        float d02 = sqrtf(bc[7] + 2.f * PD_EPS * e02 + epsq) * (1.f / NC);
        g_r[b] = ed1 + fmaxf(MARGINV - d01 - d02, 0.f) + ce;

        __threadfence();
        int o2 = atomicAdd(&g_cnt_all, 1);
        sflag2 = (o2 == BZ - 1);
        if (o2 == BZ - 1) atomicExch(&g_cnt_all, 0);
    }
    __syncthreads();

    if (sflag2 && t == 0) {
        __threadfence();
        float v = 0.f;
#pragma unroll
        for (int i = 0; i < BZ; i++) v += g_r[i];
        out[0] = v * (1.f / BZ);
    }
}

// ---------------------------------------------------------------------------
extern "C" void kernel_launch(void* const* d_in, const int* in_sizes, int n_in,
                              void* d_out, int out_size) {
    const float* pred = (const float*)d_in[0];
    const int*   cla  = (const int*)  d_in[1];
    const float* seg  = (const float*)d_in[2];
    const float* feat = (const float*)d_in[3];
    const float* W    = (const float*)d_in[4];
    const int*   idx  = (const int*)  d_in[5];
    float* out = (float*)d_out;

    // tiles 5*16*200 + w 2048 + ce 256 = 18304 floats = 73216 B
    const int smem = (NBUF * TILE_C * PADW + 4 * CPB + 256) * (int)sizeof(float);
    cudaFuncSetAttribute(k1_fused, cudaFuncAttributeMaxDynamicSharedMemorySize, smem);

    k1_fused<<<BZ * SPLITS, TPB, smem>>>(feat, W, idx, pred, cla, seg, out);
}